// round 3
// baseline (speedup 1.0000x reference)
#include <cuda_runtime.h>
#include <math.h>
#include <stdint.h>

// Problem constants
#define Bb   8
#define Nn   4096
#define Cc   1024
#define NBLK 8
#define BS   128
#define NF   4096          // complex FFT length (= N), real length 2N = 8192
#define MP   4160          // padded mode count (4097 used; 65 tiles of 64)

// Scratch (device globals; zero-initialized at module load)
__device__ __align__(16) float g_Xr[Bb * Cc * MP];
__device__ __align__(16) float g_Xi[Bb * Cc * MP];
__device__ __align__(16) float g_Hr[Bb * Cc * MP];
__device__ __align__(16) float g_Hi[Bb * Cc * MP];

// reverse 6 base-4 digits of a 12-bit index
__device__ __forceinline__ int rev4(int k) {
    return ((k & 3) << 10) | (((k >> 2) & 3) << 8) | (((k >> 4) & 3) << 6) |
           (((k >> 6) & 3) << 4) | (((k >> 8) & 3) << 2) | ((k >> 10) & 3);
}

// In-place radix-4 DIF, 6 stages, 4 channels of 4096 complex in shared.
// 512 threads: ch = tid>>7 (4 channels), 128 lanes each, 8 butterflies/lane/stage.
// Natural-order input -> digit-reversed output (element k at position rev4(k)).
__device__ __forceinline__ void fft_stages(float* sr, float* si, int tid, bool fwd) {
    const int ch = tid >> 7;
    const int lane = tid & 127;
    float* pr = sr + (ch << 12);
    float* pi = si + (ch << 12);
#pragma unroll 1
    for (int s = 0; s < 6; ++s) {
        const int lq = 10 - 2 * s;        // log2(q), q = L/4
        const int q = 1 << lq;
        const float angscale = 6.28318530717958647692f / (float)(q << 2);
        __syncthreads();
#pragma unroll
        for (int u = 0; u < 8; ++u) {
            int bi = lane + (u << 7);                 // butterfly id 0..1023
            int j = bi & (q - 1);
            int base = ((bi >> lq) << (lq + 2)) + j;  // group*L + j

            float a0r = pr[base],         a0i = pi[base];
            float a1r = pr[base + q],     a1i = pi[base + q];
            float a2r = pr[base + 2 * q], a2i = pi[base + 2 * q];
            float a3r = pr[base + 3 * q], a3i = pi[base + 3 * q];

            float t0r = a0r + a2r, t0i = a0i + a2i;
            float t1r = a0r - a2r, t1i = a0i - a2i;
            float t2r = a1r + a3r, t2i = a1i + a3i;
            float t3r = a1r - a3r, t3i = a1i - a3i;

            float b0r = t0r + t2r, b0i = t0i + t2i;
            float b2r = t0r - t2r, b2i = t0i - t2i;
            float b1r, b1i, b3r, b3i;
            if (fwd) {  // e^{-2pi i}: A1 = t1 - i t3, A3 = t1 + i t3
                b1r = t1r + t3i; b1i = t1i - t3r;
                b3r = t1r - t3i; b3i = t1i + t3r;
            } else {    // e^{+2pi i}: A1 = t1 + i t3, A3 = t1 - i t3
                b1r = t1r - t3i; b1i = t1i + t3r;
                b3r = t1r + t3i; b3i = t1i - t3r;
            }

            float ang = angscale * (float)j;          // < pi/2
            float sv, cv;
            __sincosf(ang, &sv, &cv);
            float w1r = cv, w1i = fwd ? -sv : sv;
            float w2r = w1r * w1r - w1i * w1i;
            float w2i = 2.0f * w1r * w1i;
            float w3r = w2r * w1r - w2i * w1i;
            float w3i = w2r * w1i + w2i * w1r;

            pr[base] = b0r;                pi[base] = b0i;
            pr[base + q]     = b1r * w1r - b1i * w1i;
            pi[base + q]     = b1r * w1i + b1i * w1r;
            pr[base + 2 * q] = b2r * w2r - b2i * w2i;
            pi[base + 2 * q] = b2r * w2i + b2i * w2r;
            pr[base + 3 * q] = b3r * w3r - b3i * w3i;
            pi[base + 3 * q] = b3r * w3i + b3i * w3r;
        }
    }
    __syncthreads();
}

// Forward: x[b, :, c] -> X[m] (m = 0..4096) for 4 channels per block.
__global__ void __launch_bounds__(512) afno_fft_fwd(const float* __restrict__ x) {
    extern __shared__ float sm[];
    float* sr = sm;
    float* si = sm + 4 * NF;
    const int tid = threadIdx.x;
    const int b = blockIdx.y;
    const int c0 = blockIdx.x * 4;

    // pack z[n] = x[2n] + i x[2n+1] (n < 2048), zeros above (zero padding to 2N)
    const float* xb = x + (size_t)b * Nn * Cc + c0;
    for (int idx = tid; idx < Nn * 4; idx += 512) {
        int t = idx >> 2, j = idx & 3;
        float v = xb[(size_t)t * Cc + j];
        int n = t >> 1;
        if (t & 1) si[(j << 12) + n] = v;
        else       sr[(j << 12) + n] = v;
    }
    for (int idx = tid; idx < 2048 * 4; idx += 512) {
        int n = 2048 + (idx >> 2), j = idx & 3;
        sr[(j << 12) + n] = 0.0f;
        si[(j << 12) + n] = 0.0f;
    }

    fft_stages(sr, si, tid, true);

    // unpack packed-real FFT: X[m] = (E + e^{-i pi m/4096} O) / sqrt(8192)
    const int ch = tid >> 7;
    const int lane = tid & 127;
    const float* pr = sr + (ch << 12);
    const float* pi = si + (ch << 12);
    const size_t gbase = ((size_t)b * Cc + (c0 + ch)) * MP;
    const float SC = 0.01104854345603981f;  // 1/sqrt(8192)
    for (int m = lane; m <= 4096; m += 128) {
        int m4 = m & 4095;
        int r4 = (4096 - m) & 4095;
        int pm = rev4(m4), pn = rev4(r4);
        float zmr = pr[pm], zmi = pi[pm];
        float zrr = pr[pn], zri = pi[pn];
        float Er = 0.5f * (zmr + zrr), Ei = 0.5f * (zmi - zri);
        float nr = zmr - zrr, ni = zmi + zri;         // Zm - conj(Zr)
        float Or = 0.5f * ni, Oi = -0.5f * nr;        // /(2i)
        float ang = 7.66990393942820573e-4f * (float)m;  // pi*m/4096
        float sv, cv;
        __sincosf(ang, &sv, &cv);
        float twr = cv, twi = -sv;
        float Tr = twr * Or - twi * Oi;
        float Ti = twr * Oi + twi * Or;
        g_Xr[gbase + m] = (Er + Tr) * SC;
        g_Xi[gbase + m] = (Ei + Ti) * SC;
    }
}

// Inverse: Y[m] (in g_Xr/g_Xi) -> y[t], out = y + x, 4 channels per block.
__global__ void __launch_bounds__(512) afno_fft_inv(const float* __restrict__ x,
                                                    float* __restrict__ out) {
    extern __shared__ float sm[];
    float* sr = sm;
    float* si = sm + 4 * NF;
    const int tid = threadIdx.x;
    const int b = blockIdx.y;
    const int c0 = blockIdx.x * 4;
    const int ch = tid >> 7;
    const int lane = tid & 127;
    float* pr = sr + (ch << 12);
    float* pi = si + (ch << 12);
    const size_t gbase = ((size_t)b * Cc + (c0 + ch)) * MP;

    // rebuild packed spectrum: Z'[k] = E + i * (e^{+i pi k/4096} (Yk - Y2)/2)
    for (int k = lane; k < 4096; k += 128) {
        float ykr = g_Xr[gbase + k], yki = g_Xi[gbase + k];
        int m2 = 4096 - k;                       // k=0 -> 4096 (no conj), else conj
        float sgn = (k == 0) ? 1.0f : -1.0f;
        float y2r = g_Xr[gbase + m2];
        float y2i = sgn * g_Xi[gbase + m2];
        float Er = 0.5f * (ykr + y2r), Ei = 0.5f * (yki + y2i);
        float Dr = 0.5f * (ykr - y2r), Di = 0.5f * (yki - y2i);
        float ang = 7.66990393942820573e-4f * (float)k;  // pi*k/4096
        float sv, cv;
        __sincosf(ang, &sv, &cv);
        float Odr = cv * Dr - sv * Di;
        float Odi = cv * Di + sv * Dr;
        pr[k] = Er - Odi;
        pi[k] = Ei + Odr;
    }

    fft_stages(sr, si, tid, false);

    // z[n] at sh[rev4(n)]; y[2n]=Re, y[2n+1]=Im, scale sqrt(8192)/4096
    const float SC = 0.02209708691207961f;  // sqrt(2)/64
    const float* xb = x + (size_t)b * Nn * Cc + c0;
    float* ob = out + (size_t)b * Nn * Cc + c0;
    for (int idx = tid; idx < Nn * 4; idx += 512) {
        int t = idx >> 2, j = idx & 3;
        int p = rev4(t >> 1);
        float v = (t & 1) ? si[(j << 12) + p] : sr[(j << 12) + p];
        size_t a = (size_t)t * Cc + j;
        ob[a] = v * SC + xb[a];
    }
}

// Complex block-diagonal GEMM layer. Output tile 64(m) x 128(c), K=128 in 2 chunks.
// LAYER==1: A = g_X (spectrum), C = g_H, epilogue bias+relu
// LAYER==2: A = g_H,            C = g_X, epilogue bias+softshrink
template <int LAYER>
__global__ void __launch_bounds__(256, 2) afno_gemm(const float* __restrict__ W,
                                                    const float* __restrict__ Bias) {
    extern __shared__ float sm[];
    float* Asr = sm;           // [kk][m]  64x64
    float* Asi = sm + 4096;    // [kk][m]  64x64
    float* W0s = sm + 8192;    // [kk][c]  64x128
    float* W1s = sm + 16384;   // [kk][c]  64x128

    const float* Ar = (LAYER == 1) ? g_Xr : g_Hr;
    const float* Ai = (LAYER == 1) ? g_Xi : g_Hi;
    float* Cr = (LAYER == 1) ? g_Hr : g_Xr;
    float* Ci = (LAYER == 1) ? g_Hi : g_Xi;

    const int tid = threadIdx.x;
    const int mt = blockIdx.x, kb = blockIdx.y, b = blockIdx.z;
    const int m0 = mt * 64;

    const float* ArB = Ar + ((size_t)(b * Cc + kb * BS)) * MP + m0;
    const float* AiB = Ai + ((size_t)(b * Cc + kb * BS)) * MP + m0;
    const float* W0g = W + kb * (BS * BS);            // w[0][kb][i][o]
    const float* W1g = W + (NBLK + kb) * (BS * BS);   // w[1][kb][i][o]

    const int tm = tid & 15;     // m group: 4 contiguous m
    const int tc = tid >> 4;     // c group: 8 contiguous c
    const int mLoc = tm << 2;
    const int cLoc = tc << 3;

    float accr[8][4];
    float acci[8][4];
#pragma unroll
    for (int w = 0; w < 8; ++w)
#pragma unroll
        for (int v = 0; v < 4; ++v) { accr[w][v] = 0.0f; acci[w][v] = 0.0f; }

#pragma unroll 1
    for (int kc = 0; kc < BS; kc += 64) {
        __syncthreads();
        // load A chunk (64 rows x 64 m), coalesced float4
        for (int i = tid; i < 64 * 16; i += 256) {
            int kk = i >> 4, mm = (i & 15) << 2;
            *(float4*)(Asr + kk * 64 + mm) =
                *(const float4*)(ArB + (size_t)(kc + kk) * MP + mm);
            *(float4*)(Asi + kk * 64 + mm) =
                *(const float4*)(AiB + (size_t)(kc + kk) * MP + mm);
        }
        // load W chunk (64 rows x 128 c)
        for (int i = tid; i < 64 * 32; i += 256) {
            int kk = i >> 5, cc = (i & 31) << 2;
            *(float4*)(W0s + kk * 128 + cc) = *(const float4*)(W0g + (kc + kk) * 128 + cc);
            *(float4*)(W1s + kk * 128 + cc) = *(const float4*)(W1g + (kc + kk) * 128 + cc);
        }
        __syncthreads();

#pragma unroll 1
        for (int kk = 0; kk < 64; ++kk) {
            float4 arv = *(const float4*)(Asr + kk * 64 + mLoc);
            float4 aiv = *(const float4*)(Asi + kk * 64 + mLoc);
            float4 w0a = *(const float4*)(W0s + kk * 128 + cLoc);
            float4 w0b = *(const float4*)(W0s + kk * 128 + cLoc + 4);
            float4 w1a = *(const float4*)(W1s + kk * 128 + cLoc);
            float4 w1b = *(const float4*)(W1s + kk * 128 + cLoc + 4);
            float arx[4] = {arv.x, arv.y, arv.z, arv.w};
            float aix[4] = {aiv.x, aiv.y, aiv.z, aiv.w};
            float w0x[8] = {w0a.x, w0a.y, w0a.z, w0a.w, w0b.x, w0b.y, w0b.z, w0b.w};
            float w1x[8] = {w1a.x, w1a.y, w1a.z, w1a.w, w1b.x, w1b.y, w1b.z, w1b.w};
#pragma unroll
            for (int w = 0; w < 8; ++w)
#pragma unroll
                for (int v = 0; v < 4; ++v) {
                    accr[w][v] += arx[v] * w0x[w];
                    accr[w][v] -= aix[v] * w1x[w];
                    acci[w][v] += aix[v] * w0x[w];
                    acci[w][v] += arx[v] * w1x[w];
                }
        }
    }

    // epilogue: bias + nonlinearity, coalesced float4 stores (m-contiguous)
#pragma unroll
    for (int w = 0; w < 8; ++w) {
        int c = cLoc + w;
        float br_ = Bias[kb * BS + c];
        float bi_ = Bias[NBLK * BS + kb * BS + c];
        float vr[4], vi[4];
#pragma unroll
        for (int v = 0; v < 4; ++v) {
            float fr = accr[w][v] + br_;
            float fi = acci[w][v] + bi_;
            if (LAYER == 1) {
                fr = fmaxf(fr, 0.0f);
                fi = fmaxf(fi, 0.0f);
            } else {
                fr = (fr > 0.01f) ? fr - 0.01f : ((fr < -0.01f) ? fr + 0.01f : 0.0f);
                fi = (fi > 0.01f) ? fi - 0.01f : ((fi < -0.01f) ? fi + 0.01f : 0.0f);
            }
            vr[v] = fr;
            vi[v] = fi;
        }
        size_t cb = ((size_t)(b * Cc + kb * BS + c)) * MP + m0 + mLoc;
        *(float4*)(Cr + cb) = make_float4(vr[0], vr[1], vr[2], vr[3]);
        *(float4*)(Ci + cb) = make_float4(vi[0], vi[1], vi[2], vi[3]);
    }
}

extern "C" void kernel_launch(void* const* d_in, const int* in_sizes, int n_in,
                              void* d_out, int out_size) {
    const float* x  = (const float*)d_in[0];
    const float* w1 = (const float*)d_in[1];
    const float* b1 = (const float*)d_in[2];
    const float* w2 = (const float*)d_in[3];
    const float* b2 = (const float*)d_in[4];
    float* out = (float*)d_out;

    const int FFT_SMEM = 4 * NF * 2 * (int)sizeof(float);   // 131072
    const int GEMM_SMEM = 24576 * (int)sizeof(float);       // 98304

    cudaFuncSetAttribute(afno_fft_fwd, cudaFuncAttributeMaxDynamicSharedMemorySize, FFT_SMEM);
    cudaFuncSetAttribute(afno_fft_inv, cudaFuncAttributeMaxDynamicSharedMemorySize, FFT_SMEM);
    cudaFuncSetAttribute(afno_gemm<1>, cudaFuncAttributeMaxDynamicSharedMemorySize, GEMM_SMEM);
    cudaFuncSetAttribute(afno_gemm<2>, cudaFuncAttributeMaxDynamicSharedMemorySize, GEMM_SMEM);

    dim3 fgrid(Cc / 4, Bb);
    afno_fft_fwd<<<fgrid, 512, FFT_SMEM>>>(x);

    dim3 ggrid(MP / 64, NBLK, Bb);   // 65 x 8 x 8
    afno_gemm<1><<<ggrid, 256, GEMM_SMEM>>>(w1, b1);
    afno_gemm<2><<<ggrid, 256, GEMM_SMEM>>>(w2, b2);

    afno_fft_inv<<<fgrid, 512, FFT_SMEM>>>(x, out);
}

// round 4
// speedup vs baseline: 1.0021x; 1.0021x over previous
#include <cuda_runtime.h>
#include <math.h>
#include <stdint.h>

// Problem constants
#define Bb   8
#define Nn   4096
#define Cc   1024
#define NBLK 8
#define BS   128
#define NF   4096          // complex FFT length (= N), real length 2N = 8192
#define MP   4160          // padded mode count (4097 used; 65 tiles of 64)

// Scratch (device globals; zero-initialized at module load)
__device__ __align__(16) float g_Xr[Bb * Cc * MP];
__device__ __align__(16) float g_Xi[Bb * Cc * MP];
__device__ __align__(16) float g_Hr[Bb * Cc * MP];
__device__ __align__(16) float g_Hi[Bb * Cc * MP];

// reverse 6 base-4 digits of a 12-bit index
__device__ __forceinline__ int rev4(int k) {
    return ((k & 3) << 10) | (((k >> 2) & 3) << 8) | (((k >> 4) & 3) << 6) |
           (((k >> 6) & 3) << 4) | (((k >> 8) & 3) << 2) | ((k >> 10) & 3);
}

// In-place radix-4 DIF, 6 stages, 4 channels of 4096 complex in shared.
// 512 threads: ch = tid>>7 (4 channels), 128 lanes each, 8 butterflies/lane/stage.
// Natural-order input -> digit-reversed output (element k at position rev4(k)).
__device__ __forceinline__ void fft_stages(float* sr, float* si, int tid, bool fwd) {
    const int ch = tid >> 7;
    const int lane = tid & 127;
    float* pr = sr + (ch << 12);
    float* pi = si + (ch << 12);
#pragma unroll 1
    for (int s = 0; s < 6; ++s) {
        const int lq = 10 - 2 * s;        // log2(q), q = L/4
        const int q = 1 << lq;
        const float angscale = 6.28318530717958647692f / (float)(q << 2);
        __syncthreads();
#pragma unroll
        for (int u = 0; u < 8; ++u) {
            int bi = lane + (u << 7);                 // butterfly id 0..1023
            int j = bi & (q - 1);
            int base = ((bi >> lq) << (lq + 2)) + j;  // group*L + j

            float a0r = pr[base],         a0i = pi[base];
            float a1r = pr[base + q],     a1i = pi[base + q];
            float a2r = pr[base + 2 * q], a2i = pi[base + 2 * q];
            float a3r = pr[base + 3 * q], a3i = pi[base + 3 * q];

            float t0r = a0r + a2r, t0i = a0i + a2i;
            float t1r = a0r - a2r, t1i = a0i - a2i;
            float t2r = a1r + a3r, t2i = a1i + a3i;
            float t3r = a1r - a3r, t3i = a1i - a3i;

            float b0r = t0r + t2r, b0i = t0i + t2i;
            float b2r = t0r - t2r, b2i = t0i - t2i;
            float b1r, b1i, b3r, b3i;
            if (fwd) {  // e^{-2pi i}: A1 = t1 - i t3, A3 = t1 + i t3
                b1r = t1r + t3i; b1i = t1i - t3r;
                b3r = t1r - t3i; b3i = t1i + t3r;
            } else {    // e^{+2pi i}: A1 = t1 + i t3, A3 = t1 - i t3
                b1r = t1r - t3i; b1i = t1i + t3r;
                b3r = t1r + t3i; b3i = t1i - t3r;
            }

            float ang = angscale * (float)j;          // < pi/2
            float sv, cv;
            __sincosf(ang, &sv, &cv);
            float w1r = cv, w1i = fwd ? -sv : sv;
            float w2r = w1r * w1r - w1i * w1i;
            float w2i = 2.0f * w1r * w1i;
            float w3r = w2r * w1r - w2i * w1i;
            float w3i = w2r * w1i + w2i * w1r;

            pr[base] = b0r;                pi[base] = b0i;
            pr[base + q]     = b1r * w1r - b1i * w1i;
            pi[base + q]     = b1r * w1i + b1i * w1r;
            pr[base + 2 * q] = b2r * w2r - b2i * w2i;
            pi[base + 2 * q] = b2r * w2i + b2i * w2r;
            pr[base + 3 * q] = b3r * w3r - b3i * w3i;
            pi[base + 3 * q] = b3r * w3i + b3i * w3r;
        }
    }
    __syncthreads();
}

// Forward: x[b, :, c] -> X[m] (m = 0..4096) for 4 channels per block.
__global__ void __launch_bounds__(512) afno_fft_fwd(const float* __restrict__ x) {
    extern __shared__ float sm[];
    float* sr = sm;
    float* si = sm + 4 * NF;
    const int tid = threadIdx.x;
    const int b = blockIdx.y;
    const int c0 = blockIdx.x * 4;

    // pack z[n] = x[2n] + i x[2n+1] (n < 2048), zeros above (zero padding to 2N)
    const float* xb = x + (size_t)b * Nn * Cc + c0;
    for (int idx = tid; idx < Nn * 4; idx += 512) {
        int t = idx >> 2, j = idx & 3;
        float v = xb[(size_t)t * Cc + j];
        int n = t >> 1;
        if (t & 1) si[(j << 12) + n] = v;
        else       sr[(j << 12) + n] = v;
    }
    for (int idx = tid; idx < 2048 * 4; idx += 512) {
        int n = 2048 + (idx >> 2), j = idx & 3;
        sr[(j << 12) + n] = 0.0f;
        si[(j << 12) + n] = 0.0f;
    }

    fft_stages(sr, si, tid, true);

    // unpack packed-real FFT: X[m] = (E + e^{-i pi m/4096} O) / sqrt(8192)
    const int ch = tid >> 7;
    const int lane = tid & 127;
    const float* pr = sr + (ch << 12);
    const float* pi = si + (ch << 12);
    const size_t gbase = ((size_t)b * Cc + (c0 + ch)) * MP;
    const float SC = 0.01104854345603981f;  // 1/sqrt(8192)
    for (int m = lane; m <= 4096; m += 128) {
        int m4 = m & 4095;
        int r4 = (4096 - m) & 4095;
        int pm = rev4(m4), pn = rev4(r4);
        float zmr = pr[pm], zmi = pi[pm];
        float zrr = pr[pn], zri = pi[pn];
        float Er = 0.5f * (zmr + zrr), Ei = 0.5f * (zmi - zri);
        float nr = zmr - zrr, ni = zmi + zri;         // Zm - conj(Zr)
        float Or = 0.5f * ni, Oi = -0.5f * nr;        // /(2i)
        float ang = 7.66990393942820573e-4f * (float)m;  // pi*m/4096
        float sv, cv;
        __sincosf(ang, &sv, &cv);
        float twr = cv, twi = -sv;
        float Tr = twr * Or - twi * Oi;
        float Ti = twr * Oi + twi * Or;
        g_Xr[gbase + m] = (Er + Tr) * SC;
        g_Xi[gbase + m] = (Ei + Ti) * SC;
    }
}

// Inverse: Y[m] (in g_Xr/g_Xi) -> y[t], out = y + x, 4 channels per block.
__global__ void __launch_bounds__(512) afno_fft_inv(const float* __restrict__ x,
                                                    float* __restrict__ out) {
    extern __shared__ float sm[];
    float* sr = sm;
    float* si = sm + 4 * NF;
    const int tid = threadIdx.x;
    const int b = blockIdx.y;
    const int c0 = blockIdx.x * 4;
    const int ch = tid >> 7;
    const int lane = tid & 127;
    float* pr = sr + (ch << 12);
    float* pi = si + (ch << 12);
    const size_t gbase = ((size_t)b * Cc + (c0 + ch)) * MP;

    // rebuild packed spectrum: Z'[k] = E + i * (e^{+i pi k/4096} (Yk - Y2)/2)
    for (int k = lane; k < 4096; k += 128) {
        float ykr = g_Xr[gbase + k], yki = g_Xi[gbase + k];
        int m2 = 4096 - k;                       // k=0 -> 4096 (no conj), else conj
        float sgn = (k == 0) ? 1.0f : -1.0f;
        float y2r = g_Xr[gbase + m2];
        float y2i = sgn * g_Xi[gbase + m2];
        float Er = 0.5f * (ykr + y2r), Ei = 0.5f * (yki + y2i);
        float Dr = 0.5f * (ykr - y2r), Di = 0.5f * (yki - y2i);
        float ang = 7.66990393942820573e-4f * (float)k;  // pi*k/4096
        float sv, cv;
        __sincosf(ang, &sv, &cv);
        float Odr = cv * Dr - sv * Di;
        float Odi = cv * Di + sv * Dr;
        pr[k] = Er - Odi;
        pi[k] = Ei + Odr;
    }

    fft_stages(sr, si, tid, false);

    // z[n] at sh[rev4(n)]; y[2n]=Re, y[2n+1]=Im, scale sqrt(8192)/4096
    const float SC = 0.02209708691207961f;  // sqrt(2)/64
    const float* xb = x + (size_t)b * Nn * Cc + c0;
    float* ob = out + (size_t)b * Nn * Cc + c0;
    for (int idx = tid; idx < Nn * 4; idx += 512) {
        int t = idx >> 2, j = idx & 3;
        int p = rev4(t >> 1);
        float v = (t & 1) ? si[(j << 12) + p] : sr[(j << 12) + p];
        size_t a = (size_t)t * Cc + j;
        ob[a] = v * SC + xb[a];
    }
}

// Complex block-diagonal GEMM layer. Output tile 64(m) x 128(c), K=128 in 2 chunks.
// LAYER==1: A = g_X (spectrum), C = g_H, epilogue bias+relu
// LAYER==2: A = g_H,            C = g_X, epilogue bias+softshrink
template <int LAYER>
__global__ void __launch_bounds__(256, 2) afno_gemm(const float* __restrict__ W,
                                                    const float* __restrict__ Bias) {
    extern __shared__ float sm[];
    float* Asr = sm;           // [kk][m]  64x64
    float* Asi = sm + 4096;    // [kk][m]  64x64
    float* W0s = sm + 8192;    // [kk][c]  64x128
    float* W1s = sm + 16384;   // [kk][c]  64x128

    const float* Ar = (LAYER == 1) ? g_Xr : g_Hr;
    const float* Ai = (LAYER == 1) ? g_Xi : g_Hi;
    float* Cr = (LAYER == 1) ? g_Hr : g_Xr;
    float* Ci = (LAYER == 1) ? g_Hi : g_Xi;

    const int tid = threadIdx.x;
    const int mt = blockIdx.x, kb = blockIdx.y, b = blockIdx.z;
    const int m0 = mt * 64;

    const float* ArB = Ar + ((size_t)(b * Cc + kb * BS)) * MP + m0;
    const float* AiB = Ai + ((size_t)(b * Cc + kb * BS)) * MP + m0;
    const float* W0g = W + kb * (BS * BS);            // w[0][kb][i][o]
    const float* W1g = W + (NBLK + kb) * (BS * BS);   // w[1][kb][i][o]

    const int tm = tid & 15;     // m group: 4 contiguous m
    const int tc = tid >> 4;     // c group: 8 contiguous c
    const int mLoc = tm << 2;
    const int cLoc = tc << 3;

    float accr[8][4];
    float acci[8][4];
#pragma unroll
    for (int w = 0; w < 8; ++w)
#pragma unroll
        for (int v = 0; v < 4; ++v) { accr[w][v] = 0.0f; acci[w][v] = 0.0f; }

#pragma unroll 1
    for (int kc = 0; kc < BS; kc += 64) {
        __syncthreads();
        // load A chunk (64 rows x 64 m), coalesced float4
        for (int i = tid; i < 64 * 16; i += 256) {
            int kk = i >> 4, mm = (i & 15) << 2;
            *(float4*)(Asr + kk * 64 + mm) =
                *(const float4*)(ArB + (size_t)(kc + kk) * MP + mm);
            *(float4*)(Asi + kk * 64 + mm) =
                *(const float4*)(AiB + (size_t)(kc + kk) * MP + mm);
        }
        // load W chunk (64 rows x 128 c)
        for (int i = tid; i < 64 * 32; i += 256) {
            int kk = i >> 5, cc = (i & 31) << 2;
            *(float4*)(W0s + kk * 128 + cc) = *(const float4*)(W0g + (kc + kk) * 128 + cc);
            *(float4*)(W1s + kk * 128 + cc) = *(const float4*)(W1g + (kc + kk) * 128 + cc);
        }
        __syncthreads();

#pragma unroll 1
        for (int kk = 0; kk < 64; ++kk) {
            float4 arv = *(const float4*)(Asr + kk * 64 + mLoc);
            float4 aiv = *(const float4*)(Asi + kk * 64 + mLoc);
            float4 w0a = *(const float4*)(W0s + kk * 128 + cLoc);
            float4 w0b = *(const float4*)(W0s + kk * 128 + cLoc + 4);
            float4 w1a = *(const float4*)(W1s + kk * 128 + cLoc);
            float4 w1b = *(const float4*)(W1s + kk * 128 + cLoc + 4);
            float arx[4] = {arv.x, arv.y, arv.z, arv.w};
            float aix[4] = {aiv.x, aiv.y, aiv.z, aiv.w};
            float w0x[8] = {w0a.x, w0a.y, w0a.z, w0a.w, w0b.x, w0b.y, w0b.z, w0b.w};
            float w1x[8] = {w1a.x, w1a.y, w1a.z, w1a.w, w1b.x, w1b.y, w1b.z, w1b.w};
#pragma unroll
            for (int w = 0; w < 8; ++w)
#pragma unroll
                for (int v = 0; v < 4; ++v) {
                    accr[w][v] += arx[v] * w0x[w];
                    accr[w][v] -= aix[v] * w1x[w];
                    acci[w][v] += aix[v] * w0x[w];
                    acci[w][v] += arx[v] * w1x[w];
                }
        }
    }

    // epilogue: bias + nonlinearity, coalesced float4 stores (m-contiguous)
#pragma unroll
    for (int w = 0; w < 8; ++w) {
        int c = cLoc + w;
        float br_ = Bias[kb * BS + c];
        float bi_ = Bias[NBLK * BS + kb * BS + c];
        float vr[4], vi[4];
#pragma unroll
        for (int v = 0; v < 4; ++v) {
            float fr = accr[w][v] + br_;
            float fi = acci[w][v] + bi_;
            if (LAYER == 1) {
                fr = fmaxf(fr, 0.0f);
                fi = fmaxf(fi, 0.0f);
            } else {
                fr = (fr > 0.01f) ? fr - 0.01f : ((fr < -0.01f) ? fr + 0.01f : 0.0f);
                fi = (fi > 0.01f) ? fi - 0.01f : ((fi < -0.01f) ? fi + 0.01f : 0.0f);
            }
            vr[v] = fr;
            vi[v] = fi;
        }
        size_t cb = ((size_t)(b * Cc + kb * BS + c)) * MP + m0 + mLoc;
        *(float4*)(Cr + cb) = make_float4(vr[0], vr[1], vr[2], vr[3]);
        *(float4*)(Ci + cb) = make_float4(vi[0], vi[1], vi[2], vi[3]);
    }
}

extern "C" void kernel_launch(void* const* d_in, const int* in_sizes, int n_in,
                              void* d_out, int out_size) {
    const float* x  = (const float*)d_in[0];
    const float* w1 = (const float*)d_in[1];
    const float* b1 = (const float*)d_in[2];
    const float* w2 = (const float*)d_in[3];
    const float* b2 = (const float*)d_in[4];
    float* out = (float*)d_out;

    const int FFT_SMEM = 4 * NF * 2 * (int)sizeof(float);   // 131072
    const int GEMM_SMEM = 24576 * (int)sizeof(float);       // 98304

    cudaFuncSetAttribute(afno_fft_fwd, cudaFuncAttributeMaxDynamicSharedMemorySize, FFT_SMEM);
    cudaFuncSetAttribute(afno_fft_inv, cudaFuncAttributeMaxDynamicSharedMemorySize, FFT_SMEM);
    cudaFuncSetAttribute(afno_gemm<1>, cudaFuncAttributeMaxDynamicSharedMemorySize, GEMM_SMEM);
    cudaFuncSetAttribute(afno_gemm<2>, cudaFuncAttributeMaxDynamicSharedMemorySize, GEMM_SMEM);

    dim3 fgrid(Cc / 4, Bb);
    afno_fft_fwd<<<fgrid, 512, FFT_SMEM>>>(x);

    dim3 ggrid(MP / 64, NBLK, Bb);   // 65 x 8 x 8
    afno_gemm<1><<<ggrid, 256, GEMM_SMEM>>>(w1, b1);
    afno_gemm<2><<<ggrid, 256, GEMM_SMEM>>>(w2, b2);

    afno_fft_inv<<<fgrid, 512, FFT_SMEM>>>(x, out);
}